// round 1
// baseline (speedup 1.0000x reference)
#include <cuda_runtime.h>

// Problem constants
#define NROWS   16384      // (token, codebook_num) pairs = 2048 * 8
#define KCODES  16384
#define DIMQ    32
#define DAUG    64         // augmented reduction dim: [mu*invvar | -0.5*invvar] vs [c | c^2]
#define ZLD     512        // z row length (2*DIM*cb)
#define OUT_ZHAT 524288    // 2048 * 256
#define OUT_KL   524288    // scalar at this offset
#define OUT_IDX  524289    // 16384 indices follow

// Scratch (device globals: no allocations allowed)
__device__ float g_A[DAUG * NROWS];     // 4 MB, layout [d][n]
__device__ float g_B[DAUG * KCODES];    // 4 MB, layout [d][k]
__device__ float g_bias[KCODES];        // 0.5 * sum c^2
__device__ float g_klpart[64];          // per-block kl partials (deterministic order)

// ---------------------------------------------------------------------------
// Prep A: per row n = t*8+c, d in [0,32): i = d*8+c
//   A[d][n]    = mu * invvar
//   A[32+d][n] = -0.5 * invvar
// plus kl partial sums.
// ---------------------------------------------------------------------------
__global__ void k_prepA(const float* __restrict__ z) {
    int n = blockIdx.x * blockDim.x + threadIdx.x;   // 64 blocks * 256 = 16384
    int t = n >> 3, c = n & 7;
    const float* zr = z + t * ZLD;
    float kl = 0.f;
#pragma unroll
    for (int d = 0; d < DIMQ; ++d) {
        int i = d * 8 + c;
        float mu = zr[i];
        float lv = zr[256 + i];
        lv = fminf(fmaxf(lv, -30.f), 20.f);
        float s   = expf(0.5f * lv);
        float iv  = 1.f / (s * s);      // matches reference 1/(std*std)
        float var = expf(lv);
        g_A[d * NROWS + n]          = mu * iv;
        g_A[(DIMQ + d) * NROWS + n] = -0.5f * iv;
        kl += mu * mu + var - 1.f - lv;
    }
    kl *= 1.4426f * 0.5f;

    __shared__ float red[256];
    red[threadIdx.x] = kl;
    __syncthreads();
    for (int s = 128; s > 0; s >>= 1) {
        if (threadIdx.x < s) red[threadIdx.x] += red[threadIdx.x + s];
        __syncthreads();
    }
    if (threadIdx.x == 0) g_klpart[blockIdx.x] = red[0];
}

// ---------------------------------------------------------------------------
// Prep B: B[d][k] = c[k][d], B[32+d][k] = c[k][d]^2, bias[k] = 0.5*sum c^2
// ---------------------------------------------------------------------------
__global__ void k_prepB(const float* __restrict__ codebook) {
    int k = blockIdx.x * blockDim.x + threadIdx.x;   // 16384 threads
    const float4* cb4 = reinterpret_cast<const float4*>(codebook + k * DIMQ);
    float sum2 = 0.f;
#pragma unroll
    for (int dq = 0; dq < 8; ++dq) {
        float4 v = cb4[dq];
        float vv[4] = {v.x, v.y, v.z, v.w};
#pragma unroll
        for (int j = 0; j < 4; ++j) {
            int d = dq * 4 + j;
            float cv = vv[j];
            g_B[d * KCODES + k]          = cv;
            g_B[(DIMQ + d) * KCODES + k] = cv * cv;
            sum2 += cv * cv;
        }
    }
    g_bias[k] = 0.5f * sum2;
}

// ---------------------------------------------------------------------------
// Main: fused (16384 x 16384 x 64) fp32 GEMM + per-row argmax + gather
// Block: 64 rows, loops K in tiles of 64 codes. 256 threads = 16 rg x 16 cg,
// each thread owns a 4x4 micro-tile. Tie-break = lowest code index (matches
// jnp.argmax first-max).
// ---------------------------------------------------------------------------
__global__ void __launch_bounds__(256)
k_main(const float* __restrict__ codebook, float* __restrict__ out) {
    __shared__ float As[DAUG][64];   // 16 KB, [d][row]
    __shared__ float Bs[DAUG][64];   // 16 KB, [d][code]
    __shared__ float sb[64];
    __shared__ int   win[64];

    int tid = threadIdx.x;
    int cg = tid & 15;        // code group: codes cg*4 .. cg*4+3 of the tile
    int rg = tid >> 4;        // row  group: rows  rg*4 .. rg*4+3 of the tile
    int rowbase = blockIdx.x * 64;

    // Load A tile once (rows stay resident for the whole K loop)
    for (int i = tid; i < DAUG * 16; i += 256) {
        int d = i >> 4, rq = i & 15;
        reinterpret_cast<float4*>(&As[d][0])[rq] =
            *reinterpret_cast<const float4*>(&g_A[d * NROWS + rowbase + rq * 4]);
    }

    float best[4];
    int   bidx[4];
#pragma unroll
    for (int r = 0; r < 4; ++r) { best[r] = -3.4e38f; bidx[r] = 0; }

    for (int kb = 0; kb < KCODES; kb += 64) {
        __syncthreads();   // protect previous Bs reads (and As load on iter 0)
        for (int i = tid; i < DAUG * 16; i += 256) {
            int d = i >> 4, kq = i & 15;
            reinterpret_cast<float4*>(&Bs[d][0])[kq] =
                *reinterpret_cast<const float4*>(&g_B[d * KCODES + kb + kq * 4]);
        }
        if (tid < 64) sb[tid] = g_bias[kb + tid];
        __syncthreads();

        float acc[4][4];
#pragma unroll
        for (int r = 0; r < 4; ++r)
#pragma unroll
            for (int j = 0; j < 4; ++j) acc[r][j] = 0.f;

#pragma unroll 8
        for (int d = 0; d < DAUG; ++d) {
            float4 a4 = *reinterpret_cast<const float4*>(&As[d][rg * 4]);
            float4 b4 = *reinterpret_cast<const float4*>(&Bs[d][cg * 4]);
            float av[4] = {a4.x, a4.y, a4.z, a4.w};
            float bv[4] = {b4.x, b4.y, b4.z, b4.w};
#pragma unroll
            for (int r = 0; r < 4; ++r)
#pragma unroll
                for (int j = 0; j < 4; ++j)
                    acc[r][j] += av[r] * bv[j];
        }

        // Running argmax: codes ascending within thread; strict > keeps first max
#pragma unroll
        for (int j = 0; j < 4; ++j) {
            int   k    = kb + cg * 4 + j;
            float bias = sb[cg * 4 + j];
#pragma unroll
            for (int r = 0; r < 4; ++r) {
                float s = acc[r][j] + bias;
                if (s > best[r]) { best[r] = s; bidx[r] = k; }
            }
        }
    }

    // Reduce across the 16 cg lanes of each rg (width-16 butterfly within warp)
#pragma unroll
    for (int off = 8; off > 0; off >>= 1) {
#pragma unroll
        for (int r = 0; r < 4; ++r) {
            float os = __shfl_xor_sync(0xffffffffu, best[r], off, 16);
            int   oi = __shfl_xor_sync(0xffffffffu, bidx[r], off, 16);
            if (os > best[r] || (os == best[r] && oi < bidx[r])) {
                best[r] = os; bidx[r] = oi;
            }
        }
    }
    if (cg == 0) {
#pragma unroll
        for (int r = 0; r < 4; ++r) {
            int row = rg * 4 + r;
            win[row] = bidx[r];
            out[OUT_IDX + rowbase + row] = (float)bidx[r];
        }
    }
    __syncthreads();

    // Cooperative zhat gather: out[t*256 + d*8 + c] = codebook[idx][d]
    for (int i = tid; i < 64 * DIMQ; i += 256) {
        int r = i >> 5, d = i & 31;
        int n = rowbase + r;
        int idx = win[r];
        out[(n >> 3) * 256 + d * 8 + (n & 7)] = codebook[idx * DIMQ + d];
    }
}

// ---------------------------------------------------------------------------
// Finalize kl (fixed summation order -> deterministic)
// ---------------------------------------------------------------------------
__global__ void k_fin(float* __restrict__ out) {
    float s = 0.f;
    for (int i = 0; i < 64; ++i) s += g_klpart[i];
    out[OUT_KL] = s * (1.0f / 16384.0f);   // mean over [2048, 8] * LAM(=1)
}

extern "C" void kernel_launch(void* const* d_in, const int* in_sizes, int n_in,
                              void* d_out, int out_size) {
    const float* z        = (const float*)d_in[0];
    // d_in[1] = noise: provably unused (STE forward value == zhat_v)
    const float* codebook = (const float*)d_in[2];
    float* out = (float*)d_out;

    k_prepA<<<64, 256>>>(z);
    k_prepB<<<64, 256>>>(codebook);
    k_main<<<256, 256>>>(codebook, out);
    k_fin<<<1, 1>>>(out);
}

// round 2
// speedup vs baseline: 1.2857x; 1.2857x over previous
#include <cuda_runtime.h>

// Problem constants
#define NROWS   16384      // (token, codebook_num) pairs = 2048 * 8
#define KCODES  16384
#define DIMQ    32
#define DAUG    64         // augmented reduction dim: [mu*invvar | -0.5*invvar] vs [c | c^2]
#define ZLD     512        // z row length (2*DIM*cb)
#define OUT_KL   524288    // scalar at this offset
#define OUT_IDX  524289    // 16384 indices follow

// Scratch (device globals: no allocations allowed)
__device__ float g_A[DAUG * NROWS];     // 4 MB, layout [d][n]
__device__ float g_B[DAUG * KCODES];    // 4 MB, layout [d][k]
__device__ float g_bias[KCODES];        // 0.5 * sum c^2
__device__ float g_klpart[64];          // per-block kl partials (deterministic order)

// Packed dual fp32 FMA (sm_103a FFMA2) — exact IEEE fp32 on both lanes.
#define FMA2(d_, a_, b_) asm("fma.rn.f32x2 %0, %1, %2, %0;" : "+l"(d_) : "l"(a_), "l"(b_))

// Dynamic smem layout: As2 [64][128] floats (dup pairs, 32KB) | Bs [64][256] (64KB) | win[64]
#define SM_AS2   0
#define SM_BS    (64 * 128)
#define SM_WIN   (64 * 128 + 64 * 256)
#define SMEM_BYTES ((64 * 128 + 64 * 256 + 64) * 4)

// ---------------------------------------------------------------------------
// Prep A: per row n = t*8+c, d in [0,32): i = d*8+c
//   A[d][n] = mu*invvar ; A[32+d][n] = -0.5*invvar ; plus kl partials.
// ---------------------------------------------------------------------------
__global__ void k_prepA(const float* __restrict__ z) {
    int n = blockIdx.x * blockDim.x + threadIdx.x;   // 64 blocks * 256 = 16384
    int t = n >> 3, c = n & 7;
    const float* zr = z + t * ZLD;
    float kl = 0.f;
#pragma unroll
    for (int d = 0; d < DIMQ; ++d) {
        int i = d * 8 + c;
        float mu = zr[i];
        float lv = zr[256 + i];
        lv = fminf(fmaxf(lv, -30.f), 20.f);
        float s   = expf(0.5f * lv);
        float iv  = 1.f / (s * s);      // matches reference 1/(std*std)
        float var = expf(lv);
        g_A[d * NROWS + n]          = mu * iv;
        g_A[(DIMQ + d) * NROWS + n] = -0.5f * iv;
        kl += mu * mu + var - 1.f - lv;
    }
    kl *= 1.4426f * 0.5f;

    __shared__ float red[256];
    red[threadIdx.x] = kl;
    __syncthreads();
    for (int s = 128; s > 0; s >>= 1) {
        if (threadIdx.x < s) red[threadIdx.x] += red[threadIdx.x + s];
        __syncthreads();
    }
    if (threadIdx.x == 0) g_klpart[blockIdx.x] = red[0];
}

// ---------------------------------------------------------------------------
// Prep B: B[d][k] = c[k][d], B[32+d][k] = c[k][d]^2, bias[k] = 0.5*sum c^2
// ---------------------------------------------------------------------------
__global__ void k_prepB(const float* __restrict__ codebook) {
    int k = blockIdx.x * blockDim.x + threadIdx.x;
    const float4* cb4 = reinterpret_cast<const float4*>(codebook + k * DIMQ);
    float sum2 = 0.f;
#pragma unroll
    for (int dq = 0; dq < 8; ++dq) {
        float4 v = cb4[dq];
        float vv[4] = {v.x, v.y, v.z, v.w};
#pragma unroll
        for (int j = 0; j < 4; ++j) {
            int d = dq * 4 + j;
            float cv = vv[j];
            g_B[d * KCODES + k]          = cv;
            g_B[(DIMQ + d) * KCODES + k] = cv * cv;
            sum2 += cv * cv;
        }
    }
    g_bias[k] = 0.5f * sum2;
}

// ---------------------------------------------------------------------------
// Main: fused (16384 x 16384 x 64) fp32 GEMM (FFMA2) + per-row argmax + gather
// 128 threads = 8 rg x 16 cg; micro-tile 8 rows x 16 codes per thread, codes
// packed in f32x2 pairs. A tile stored DUPLICATED in shared so broadcast pairs
// come straight from ld.shared.v2.u64. Bias folded into acc init.
// Code slot of thread cg, chunk q: tile codes q*64 + cg*4 .. +3 (2-phase
// conflict-free LDS). Tie-break = lowest code index everywhere.
// ---------------------------------------------------------------------------
__global__ void __launch_bounds__(128)
k_main(const float* __restrict__ codebook, float* __restrict__ out) {
    extern __shared__ float sm[];
    float* As2 = sm + SM_AS2;        // [d][128]: row r dup at 2r, 2r+1
    float* Bs  = sm + SM_BS;         // [d][256]
    int*   win = (int*)(sm + SM_WIN);

    int tid = threadIdx.x;
    int cg = tid & 15;
    int rg = tid >> 4;               // 0..7
    int rowbase = blockIdx.x * 64;

    // Load A tile (64 rows x 64 d), duplicated pairs
    for (int i = tid; i < 64 * 64; i += 128) {
        int d = i >> 6, r = i & 63;
        float v = g_A[d * NROWS + rowbase + r];
        As2[d * 128 + 2 * r]     = v;
        As2[d * 128 + 2 * r + 1] = v;
    }

    float best[8];
    int   bidx[8];
#pragma unroll
    for (int r = 0; r < 8; ++r) { best[r] = -3.4e38f; bidx[r] = 0; }

    const float4*     gB4    = (const float4*)g_B;
    const ulonglong2* gbias2 = (const ulonglong2*)g_bias;

    for (int kb = 0; kb < KCODES; kb += 256) {
        __syncthreads();   // previous Bs reads done (and As2 writes on iter 0)
        // Load B tile: 64 d x 256 codes (64KB), two 16-deep prefetch batches
        {
            float4 tmp[16];
#pragma unroll
            for (int u = 0; u < 16; ++u) {
                int i = tid + 128 * u;
                tmp[u] = gB4[(i >> 6) * (KCODES / 4) + (kb >> 2) + (i & 63)];
            }
#pragma unroll
            for (int u = 0; u < 16; ++u) {
                int i = tid + 128 * u;
                ((float4*)(Bs + (i >> 6) * 256))[i & 63] = tmp[u];
            }
#pragma unroll
            for (int u = 16; u < 32; ++u) {
                int i = tid + 128 * u;
                tmp[u - 16] = gB4[(i >> 6) * (KCODES / 4) + (kb >> 2) + (i & 63)];
            }
#pragma unroll
            for (int u = 16; u < 32; ++u) {
                int i = tid + 128 * u;
                ((float4*)(Bs + (i >> 6) * 256))[i & 63] = tmp[u - 16];
            }
        }
        __syncthreads();

        // Accumulators: [8 rows][4 code-chunks][2 pairs], init = bias
        unsigned long long acc[8][4][2];
#pragma unroll
        for (int q = 0; q < 4; ++q) {
            ulonglong2 bv = gbias2[(kb >> 2) + q * 16 + cg];
#pragma unroll
            for (int r = 0; r < 8; ++r) { acc[r][q][0] = bv.x; acc[r][q][1] = bv.y; }
        }

        const float* ap = As2 + rg * 16;
        const float* bp = Bs + cg * 4;
#pragma unroll 4
        for (int d = 0; d < DAUG; ++d) {
            ulonglong2 a01 = *(const ulonglong2*)(ap + d * 128);
            ulonglong2 a23 = *(const ulonglong2*)(ap + d * 128 + 4);
            ulonglong2 a45 = *(const ulonglong2*)(ap + d * 128 + 8);
            ulonglong2 a67 = *(const ulonglong2*)(ap + d * 128 + 12);
            unsigned long long a[8] = {a01.x, a01.y, a23.x, a23.y,
                                       a45.x, a45.y, a67.x, a67.y};
            unsigned long long b[4][2];
#pragma unroll
            for (int q = 0; q < 4; ++q) {
                ulonglong2 bq = *(const ulonglong2*)(bp + d * 256 + q * 64);
                b[q][0] = bq.x; b[q][1] = bq.y;
            }
#pragma unroll
            for (int r = 0; r < 8; ++r)
#pragma unroll
                for (int q = 0; q < 4; ++q) {
                    FMA2(acc[r][q][0], a[r], b[q][0]);
                    FMA2(acc[r][q][1], a[r], b[q][1]);
                }
        }

        // Running argmax; within-thread codes visited in ascending k, strict >
#pragma unroll
        for (int q = 0; q < 4; ++q)
#pragma unroll
            for (int p = 0; p < 2; ++p) {
                int kk = kb + q * 64 + cg * 4 + 2 * p;
#pragma unroll
                for (int r = 0; r < 8; ++r) {
                    unsigned long long v = acc[r][q][p];
                    float s0 = __uint_as_float((unsigned)v);
                    float s1 = __uint_as_float((unsigned)(v >> 32));
                    if (s0 > best[r]) { best[r] = s0; bidx[r] = kk; }
                    if (s1 > best[r]) { best[r] = s1; bidx[r] = kk + 1; }
                }
            }
    }

    // Reduce across the 16 cg lanes (codes interleaved -> min-index tie-break)
#pragma unroll
    for (int off = 8; off > 0; off >>= 1)
#pragma unroll
        for (int r = 0; r < 8; ++r) {
            float os = __shfl_xor_sync(0xffffffffu, best[r], off, 16);
            int   oi = __shfl_xor_sync(0xffffffffu, bidx[r], off, 16);
            if (os > best[r] || (os == best[r] && oi < bidx[r])) {
                best[r] = os; bidx[r] = oi;
            }
        }
    __syncthreads();
    if (cg == 0) {
#pragma unroll
        for (int r = 0; r < 8; ++r) {
            int row = rg * 8 + r;
            win[row] = bidx[r];
            out[OUT_IDX + rowbase + row] = (float)bidx[r];
        }
    }
    __syncthreads();

    // Cooperative zhat gather: out[t*256 + d*8 + c] = codebook[idx][d]
    for (int i = tid; i < 64 * DIMQ; i += 128) {
        int r = i >> 5, d = i & 31;
        int n = rowbase + r;
        out[(n >> 3) * 256 + d * 8 + (n & 7)] = codebook[win[r] * DIMQ + d];
    }
}

// ---------------------------------------------------------------------------
// Finalize kl (fixed summation order -> deterministic)
// ---------------------------------------------------------------------------
__global__ void k_fin(float* __restrict__ out) {
    float s = 0.f;
    for (int i = 0; i < 64; ++i) s += g_klpart[i];
    out[OUT_KL] = s * (1.0f / 16384.0f);   // mean over [2048, 8] * LAM(=1)
}

extern "C" void kernel_launch(void* const* d_in, const int* in_sizes, int n_in,
                              void* d_out, int out_size) {
    const float* z        = (const float*)d_in[0];
    // d_in[1] = noise: provably unused (STE forward value == zhat_v)
    const float* codebook = (const float*)d_in[2];
    float* out = (float*)d_out;

    cudaFuncSetAttribute(k_main, cudaFuncAttributeMaxDynamicSharedMemorySize,
                         SMEM_BYTES);

    k_prepA<<<64, 256>>>(z);
    k_prepB<<<64, 256>>>(codebook);
    k_main<<<256, 128, SMEM_BYTES>>>(codebook, out);
    k_fin<<<1, 1>>>(out);
}

// round 6
// speedup vs baseline: 3.7463x; 2.9139x over previous
#include <cuda_runtime.h>
#include <cuda_fp16.h>
#include <cstdint>

// Problem constants
#define NROWS   16384
#define KCODES  16384
#define ZLD     512
#define OUT_KL  524288
#define OUT_IDX 524289
#define KH      192        // K_eff halves per row: [h | h | m] x [h | m | h]
#define ROWB    384        // row stride bytes (192 * 2)
#define NCH     24         // 16B chunks per row

// Device-global scratch (no allocations allowed)
__device__ __align__(128) __half g_Afp[NROWS * KH];   // 6.3 MB
__device__ __align__(128) __half g_Bfp[KCODES * KH];  // 6.3 MB
__device__ __align__(128) float  g_bias[KCODES];      // 0.5 * sum c^2 (fp32)
__device__ float g_klpart[64];

// ---------------------------------------------------------------------------
// PTX helpers (all baseline sm_80/75 features — no 'a'-gated instructions)
// ---------------------------------------------------------------------------
__device__ __forceinline__ uint32_t smem_u32(const void* p) {
    uint32_t a;
    asm("{ .reg .u64 t; cvta.to.shared.u64 t, %1; cvt.u32.u64 %0, t; }"
        : "=r"(a) : "l"(p));
    return a;
}
#define CPA16(dst, src) \
    asm volatile("cp.async.cg.shared.global [%0], [%1], 16;" :: "r"(dst), "l"(src))
#define CPA_COMMIT() asm volatile("cp.async.commit_group;" ::: "memory")
#define CPA_WAIT(n)  asm volatile("cp.async.wait_group %0;" :: "n"(n) : "memory")

#define LDSM4(r0, r1, r2, r3, addr) \
    asm volatile("ldmatrix.sync.aligned.m8n8.x4.shared.b16 {%0,%1,%2,%3}, [%4];" \
        : "=r"(r0), "=r"(r1), "=r"(r2), "=r"(r3) : "r"(addr))

#define MMA16816(c, a, b0, b1) \
    asm volatile("mma.sync.aligned.m16n8k16.row.col.f32.f16.f16.f32 " \
        "{%0,%1,%2,%3}, {%4,%5,%6,%7}, {%8,%9}, {%0,%1,%2,%3};" \
        : "+f"((c)[0]), "+f"((c)[1]), "+f"((c)[2]), "+f"((c)[3]) \
        : "r"((a)[0]), "r"((a)[1]), "r"((a)[2]), "r"((a)[3]), "r"(b0), "r"(b1))

// SMEM layout (bytes)
#define SA     0                      // A tile: 128 x 384 = 49152
#define SB     49152                  // B bufs: 2 x 49152
#define SBIAS  (SB + 2 * 49152)       // 2 x 512
#define SRED   (SBIAS + 1024)         // 2 x (128 f32 + 128 i32) = 2048
#define SMEM_BYTES (SRED + 2048)

// ---------------------------------------------------------------------------
// fp16x2 split
// ---------------------------------------------------------------------------
__device__ __forceinline__ void split2(float a, __half& h, __half& m) {
    h = __float2half_rn(a);
    m = __float2half_rn(a - __half2float(h));
}

// ---------------------------------------------------------------------------
// Prep A: row n = t*8+c; aug row = [mu*invvar (32) | -0.5*invvar (32)],
// columns: [0:64]=h, [64:128]=h, [128:192]=m. Plus kl partials.
// ---------------------------------------------------------------------------
__global__ void k_prepA(const float* __restrict__ z) {
    int n = blockIdx.x * blockDim.x + threadIdx.x;
    int t = n >> 3, c = n & 7;
    const float* zr = z + t * ZLD;
    size_t base = (size_t)n * KH;
    float kl = 0.f;
#pragma unroll
    for (int d = 0; d < 32; ++d) {
        int i = d * 8 + c;
        float mu = zr[i];
        float lv = zr[256 + i];
        lv = fminf(fmaxf(lv, -30.f), 20.f);
        float s  = expf(0.5f * lv);
        float iv = 1.f / (s * s);
        float var = expf(lv);
        __half h, m;
        split2(mu * iv, h, m);
        g_Afp[base + d] = h; g_Afp[base + 64 + d] = h; g_Afp[base + 128 + d] = m;
        split2(-0.5f * iv, h, m);
        g_Afp[base + 32 + d] = h; g_Afp[base + 96 + d] = h; g_Afp[base + 160 + d] = m;
        kl += mu * mu + var - 1.f - lv;
    }
    kl *= 1.4426f * 0.5f;

    __shared__ float red[256];
    red[threadIdx.x] = kl;
    __syncthreads();
    for (int s = 128; s > 0; s >>= 1) {
        if (threadIdx.x < s) red[threadIdx.x] += red[threadIdx.x + s];
        __syncthreads();
    }
    if (threadIdx.x == 0) g_klpart[blockIdx.x] = red[0];
}

// ---------------------------------------------------------------------------
// Prep B: aug row k = [c (32) | c^2 (32)], columns [0:64]=h, [64:128]=m,
// [128:192]=h. bias = 0.5*sum c^2 (fp32).
// ---------------------------------------------------------------------------
__global__ void k_prepB(const float* __restrict__ codebook) {
    int k = blockIdx.x * blockDim.x + threadIdx.x;
    size_t base = (size_t)k * KH;
    float sum2 = 0.f;
#pragma unroll
    for (int d = 0; d < 32; ++d) {
        float cv = codebook[k * 32 + d];
        __half h, m;
        split2(cv, h, m);
        g_Bfp[base + d] = h; g_Bfp[base + 64 + d] = m; g_Bfp[base + 128 + d] = h;
        split2(cv * cv, h, m);
        g_Bfp[base + 32 + d] = h; g_Bfp[base + 96 + d] = m; g_Bfp[base + 160 + d] = h;
        sum2 += cv * cv;
    }
    g_bias[k] = 0.5f * sum2;
}

// ---------------------------------------------------------------------------
// cp.async one B chunk (128 codes x 24 chunks, XOR-swizzled) + bias
// ---------------------------------------------------------------------------
__device__ __forceinline__ void load_B_chunk(uint32_t sbase, int ci, int s, int tid) {
    const char* gB = (const char*)g_Bfp + (size_t)ci * 128 * ROWB;
    uint32_t bb = sbase + SB + s * 49152;
#pragma unroll
    for (int u = 0; u < 12; ++u) {
        int idx = tid + 256 * u;           // 0..3071
        int r = idx / NCH, c = idx % NCH;
        CPA16(bb + r * ROWB + ((c ^ (r & 7)) << 4), gB + r * ROWB + c * 16);
    }
    if (tid < 32)
        CPA16(sbase + SBIAS + s * 512 + tid * 16,
              (const char*)g_bias + (size_t)ci * 512 + tid * 16);
}

// ---------------------------------------------------------------------------
// Main: 128 CTAs x 128 rows; loop 128 chunks of 128 codes.
// 256 threads = 8 warps: rg = w&3 (rows rg*32..+31), cg = w>>2 (cols cg*64..+63).
// Per warp: 2 mtiles x 8 ntiles of m16n8k16, K = 192 (12 k-steps).
// Running per-row argmax with bias; tie-break = lowest code index.
// ---------------------------------------------------------------------------
__global__ void __launch_bounds__(256)
k_main(const float* __restrict__ codebook, float* __restrict__ out) {
    extern __shared__ char smem[];
    uint32_t sbase = smem_u32(smem);
    int tid = threadIdx.x, lane = tid & 31, w = tid >> 5;
    int rg = w & 3, cg = w >> 2;
    int rowbase = blockIdx.x * 128;

    // Prologue: A tile + B chunks 0,1
    {
        const char* gA = (const char*)g_Afp + (size_t)rowbase * ROWB;
#pragma unroll
        for (int u = 0; u < 12; ++u) {
            int idx = tid + 256 * u;
            int r = idx / NCH, c = idx % NCH;
            CPA16(sbase + SA + r * ROWB + ((c ^ (r & 7)) << 4), gA + r * ROWB + c * 16);
        }
        CPA_COMMIT();
        load_B_chunk(sbase, 0, 0, tid); CPA_COMMIT();
        load_B_chunk(sbase, 1, 1, tid); CPA_COMMIT();
        CPA_WAIT(1);               // A + B0 complete
        __syncthreads();
    }

    // Per-lane ldmatrix constants
    int e     = lane & 7;
    int msel  = lane >> 3;
    int aX    = ((msel >> 1) & 1) << 4;     // A khi selector
    int bX    = (msel & 1) << 4;            // B khi selector
    int aRow  = ((msel & 1) << 3) + e;      // A row within 16
    int bRAdd = (msel & 2) ? 8 : 0;         // B ntile-odd row offset
    uint32_t aBase0 = sbase + SA + (rg * 32 + aRow) * ROWB;
    uint32_t aBase1 = aBase0 + 16 * ROWB;
    uint32_t bBase[4];
#pragma unroll
    for (int j = 0; j < 4; ++j)
        bBase[j] = sbase + SB + (cg * 64 + 16 * j + bRAdd + e) * ROWB;

    float best[4];
    int   bidx[4];
#pragma unroll
    for (int q = 0; q < 4; ++q) { best[q] = -3.4e38f; bidx[q] = 0; }

    for (int ci = 0; ci < 128; ++ci) {
        int s = ci & 1;
        uint32_t sOff = s * 49152;

        // bias (fp32) for this warp's 16 (ntile, col-pair) slots
        float2 bs[8];
#pragma unroll
        for (int nt = 0; nt < 8; ++nt)
            bs[nt] = *(const float2*)(smem + SBIAS + s * 512
                                      + (cg * 64 + nt * 8 + 2 * (lane & 3)) * 4);

        float acc[2][8][4];
#pragma unroll
        for (int mt = 0; mt < 2; ++mt)
#pragma unroll
            for (int nt = 0; nt < 8; ++nt)
#pragma unroll
                for (int i = 0; i < 4; ++i) acc[mt][nt][i] = 0.f;

#pragma unroll
        for (int ks = 0; ks < 12; ++ks) {
            uint32_t offlo = (uint32_t)(((2 * ks) ^ e) << 4);
            uint32_t offA = offlo ^ aX, offB = offlo ^ bX;
            uint32_t ra0[4], ra1[4];
            LDSM4(ra0[0], ra0[1], ra0[2], ra0[3], aBase0 + offA);
            LDSM4(ra1[0], ra1[1], ra1[2], ra1[3], aBase1 + offA);
#pragma unroll
            for (int j = 0; j < 4; ++j) {
                uint32_t rb0, rb1, rb2, rb3;
                LDSM4(rb0, rb1, rb2, rb3, bBase[j] + sOff + offB);
                MMA16816(acc[0][2 * j],     ra0, rb0, rb1);
                MMA16816(acc[0][2 * j + 1], ra0, rb2, rb3);
                MMA16816(acc[1][2 * j],     ra1, rb0, rb1);
                MMA16816(acc[1][2 * j + 1], ra1, rb2, rb3);
            }
        }

        // Running argmax (candidates ascending in k within each chain)
        int kbase = ci * 128 + cg * 64 + 2 * (lane & 3);
#pragma unroll
        for (int nt = 0; nt < 8; ++nt) {
            int kc = kbase + nt * 8;
#pragma unroll
            for (int mt = 0; mt < 2; ++mt) {
                float v0 = acc[mt][nt][0] + bs[nt].x;
                float v1 = acc[mt][nt][1] + bs[nt].y;
                float v2 = acc[mt][nt][2] + bs[nt].x;
                float v3 = acc[mt][nt][3] + bs[nt].y;
                int q0 = mt * 2, q1 = mt * 2 + 1;
                if (v0 > best[q0]) { best[q0] = v0; bidx[q0] = kc; }
                if (v1 > best[q0]) { best[q0] = v1; bidx[q0] = kc + 1; }
                if (v2 > best[q1]) { best[q1] = v2; bidx[q1] = kc; }
                if (v3 > best[q1]) { best[q1] = v3; bidx[q1] = kc + 1; }
            }
        }

        __syncthreads();                       // all warps done reading buf s
        if (ci + 2 < 128) {
            load_B_chunk(sbase, ci + 2, s, tid);
            CPA_COMMIT();
            CPA_WAIT(1);                       // next chunk (ci+1) complete
        } else {
            CPA_WAIT(0);
        }
        __syncthreads();
    }

    // Quad reduce (lanes sharing rows differ only in cols; min-index ties)
#pragma unroll
    for (int off = 1; off <= 2; off <<= 1)
#pragma unroll
        for (int q = 0; q < 4; ++q) {
            float os = __shfl_xor_sync(0xffffffffu, best[q], off);
            int   oi = __shfl_xor_sync(0xffffffffu, bidx[q], off);
            if (os > best[q] || (os == best[q] && oi < bidx[q])) {
                best[q] = os; bidx[q] = oi;
            }
        }
    float* sredv = (float*)(smem + SRED);
    int*   sredi = (int*)(smem + SRED + 1024);
    if ((lane & 3) == 0) {
#pragma unroll
        for (int mt = 0; mt < 2; ++mt)
#pragma unroll
            for (int h = 0; h < 2; ++h) {
                int row = rg * 32 + mt * 16 + h * 8 + (lane >> 2);
                sredv[cg * 128 + row] = best[mt * 2 + h];
                sredi[cg * 128 + row] = bidx[mt * 2 + h];
            }
    }
    __syncthreads();

    // Final per-row merge (2 col-groups) + outputs
    if (tid < 128) {
        float v0 = sredv[tid], v1 = sredv[128 + tid];
        int   i0 = sredi[tid], i1 = sredi[128 + tid];
        int bi = (v1 > v0 || (v1 == v0 && i1 < i0)) ? i1 : i0;

        int n = rowbase + tid;
        out[OUT_IDX + n] = (float)bi;
        const float4* cb = (const float4*)(codebook + (size_t)bi * 32);
        int obase = (n >> 3) * 256 + (n & 7);
#pragma unroll
        for (int dq = 0; dq < 8; ++dq) {
            float4 v = cb[dq];
            out[obase + (dq * 4 + 0) * 8] = v.x;
            out[obase + (dq * 4 + 1) * 8] = v.y;
            out[obase + (dq * 4 + 2) * 8] = v.z;
            out[obase + (dq * 4 + 3) * 8] = v.w;
        }
    }
}

// ---------------------------------------------------------------------------
// Finalize kl (fixed order -> deterministic)
// ---------------------------------------------------------------------------
__global__ void k_fin(float* __restrict__ out) {
    float s = 0.f;
    for (int i = 0; i < 64; ++i) s += g_klpart[i];
    out[OUT_KL] = s * (1.0f / 16384.0f);
}

extern "C" void kernel_launch(void* const* d_in, const int* in_sizes, int n_in,
                              void* d_out, int out_size) {
    const float* z        = (const float*)d_in[0];
    // d_in[1] = noise: unused (STE forward value == zhat_v)
    const float* codebook = (const float*)d_in[2];
    float* out = (float*)d_out;

    cudaFuncSetAttribute(k_main, cudaFuncAttributeMaxDynamicSharedMemorySize,
                         SMEM_BYTES);

    k_prepA<<<64, 256>>>(z);
    k_prepB<<<64, 256>>>(codebook);
    k_main<<<128, 256, SMEM_BYTES>>>(codebook, out);
    k_fin<<<1, 1>>>(out);
}